// round 15
// baseline (speedup 1.0000x reference)
#include <cuda_runtime.h>
#include <cuda_fp16.h>
#include <math.h>
#include <stdint.h>

#define D_TOT 2304
#define OUTC  512
#define INC   256
#define HWX   3136          // 56*56
#define NIMG  16
#define NPIX  (NIMG*HWX)    // 50176

#define BK    32
#define NITER (D_TOT/BK)    // 72
#define MT    128           // CTA M tile (channels)
#define NT    128           // CTA N tile (pixels)

// B-only 4-stage cp.async ring (A streams L2->registers via LDG.128).
#define A_STAGE_U32 2048    // g_Wa per-iter stride (unchanged layout)
#define B_PIX_U32   24      // 16 used + 8 pad (conflict-free LDS.64 banks)
#define STAGE_U32   (128*B_PIX_U32)     // 3072
#define STAGE_BYTES (STAGE_U32*4)       // 12288
#define NSTAGE      4
#define SMEM_BYTES  (NSTAGE*STAGE_BYTES)   // 49152

// scratch (device globals: no allocation allowed)
__device__ int      g_kidx[OUTC];
__device__ unsigned g_maxenc[D_TOT];   // order-preserving encoded maxima
__device__ float    g_mul[OUTC];
__device__ int      g_sel[OUTC];
__device__ int      g_active;
// A fragment stream: [mt(4)][iter(72)][2048 u32] = 2.36 MB (L2-resident)
__device__ __align__(16) uint32_t g_Wa[4 * NITER * A_STAGE_U32];
// x tiled half, pair-interleaved per 16-group: [cchunk(8)][pixel][32ch] = 25.7 MB
__device__ __align__(16) __half g_xt[(size_t)8 * NPIX * 32];

// ============================ helpers ========================================
__device__ __forceinline__ uint32_t smem_u32(const void* p) {
    uint32_t a;
    asm("{ .reg .u64 t; cvta.to.shared.u64 t, %1; cvt.u32.u64 %0, t; }"
        : "=r"(a) : "l"(p));
    return a;
}
__device__ __forceinline__ void cp16z(uint32_t dst, const void* src, uint32_t sz) {
    asm volatile("cp.async.cg.shared.global [%0], [%1], 16, %2;"
                 :: "r"(dst), "l"(src), "r"(sz) : "memory");
}
#define CP_COMMIT() asm volatile("cp.async.commit_group;" ::: "memory")
#define CP_WAIT(n)  asm volatile("cp.async.wait_group %0;" :: "n"(n) : "memory")

__device__ __forceinline__ uint32_t packh2(float lo, float hi) {
    __half2 h = __floats2half2_rn(lo, hi);
    return *reinterpret_cast<uint32_t*>(&h);
}
__device__ __forceinline__ void mma16(float* c, const uint32_t* a, const uint32_t* b) {
    asm volatile(
        "mma.sync.aligned.m16n8k16.row.col.f32.f16.f16.f32 "
        "{%0,%1,%2,%3}, {%4,%5,%6,%7}, {%8,%9}, {%0,%1,%2,%3};\n"
        : "+f"(c[0]), "+f"(c[1]), "+f"(c[2]), "+f"(c[3])
        : "r"(a[0]), "r"(a[1]), "r"(a[2]), "r"(a[3]), "r"(b[0]), "r"(b[1]));
}
// order-preserving float<->uint encoding (monotone under unsigned compare)
__device__ __forceinline__ unsigned encf(float f) {
    int i = __float_as_int(f);
    return (i >= 0) ? ((unsigned)i ^ 0x80000000u) : ~(unsigned)i;
}
__device__ __forceinline__ float decf(unsigned u) {
    return (u & 0x80000000u) ? __int_as_float((int)(u ^ 0x80000000u))
                             : __int_as_float((int)~u);
}

// ============================ small kernels ==================================
__global__ void __launch_bounds__(256) hash_kernels(const float* __restrict__ W,
                                                    const float* __restrict__ a) {
    const int o   = blockIdx.x;
    const int tid = threadIdx.x;
    // re-init encoded maxima each launch (graph-replay safe; runs before x2tile)
    if (o == 0) {
        for (int i = tid; i < D_TOT; i += 256) g_maxenc[i] = 0u;
    }
    const float* w = W + (size_t)o * D_TOT;
    float dot = 0.f, n2 = 0.f;
    for (int i = tid; i < D_TOT; i += 256) {
        float v = w[i];
        dot += a[i] * v;
        n2  += v * v;
    }
    __shared__ float s1[256], s2[256];
    s1[tid] = dot; s2[tid] = n2;
    __syncthreads();
    for (int st = 128; st > 0; st >>= 1) {
        if (tid < st) { s1[tid] += s1[tid+st]; s2[tid] += s2[tid+st]; }
        __syncthreads();
    }
    if (tid == 0) {
        float acc = s1[0];
        float pw  = s2[0];
        acc += a[D_TOT+0] * pw; pw *= pw;
        acc += a[D_TOT+1] * pw; pw *= pw;
        acc += a[D_TOT+2] * pw; pw *= pw;
        acc += a[D_TOT+3] * pw; pw *= pw;
        acc += a[D_TOT+4] * pw;
        float h = floorf(acc);
        float r = fmodf(h, 16.f);
        if (r < 0.f) r += 16.f;
        g_kidx[o] = (int)r;
    }
}

__global__ void __launch_bounds__(512) build_route(const float* __restrict__ a) {
    const int tid = threadIdx.x;
    __shared__ float red[512];

    // decode maxima (+ pad-zero fmax for off-center taps)
    float v0[5];
#pragma unroll
    for (int e = 0; e < 5; e++) {
        int i = tid + e * 512;          // covers 2560 >= 2304
        float v = 0.f;
        if (i < D_TOT) {
            v = decf(g_maxenc[i]);
            if ((i >> 8) != 4) v = fmaxf(v, 0.f);
        }
        v0[e] = v;
    }

    float ss = 0.f;
#pragma unroll
    for (int e = 0; e < 5; e++) ss += v0[e] * v0[e];
    red[tid] = ss; __syncthreads();
    for (int st = 256; st > 0; st >>= 1) { if (tid < st) red[tid] += red[tid+st]; __syncthreads(); }
    __shared__ float s_norm;
    if (tid == 0) s_norm = sqrtf(red[0]);
    __syncthreads();

    float dot = 0.f;
#pragma unroll
    for (int e = 0; e < 5; e++) {
        int i = tid + e * 512;
        if (i < D_TOT) dot += a[i] * v0[e];
    }
    red[tid] = dot; __syncthreads();
    for (int st = 256; st > 0; st >>= 1) { if (tid < st) red[tid] += red[tid+st]; __syncthreads(); }

    __shared__ int s_q, s_cnt, s_pos;
    if (tid == 0) {
        float hs = 0.5f * (a[D_TOT] + a[D_TOT+1] + a[D_TOT+2] + a[D_TOT+3] + a[D_TOT+4]);
        float acc = red[0] / s_norm + hs;
        float h = floorf(acc);
        float r = fmodf(h, 16.f);
        if (r < 0.f) r += 16.f;
        s_q = (int)r;
        s_cnt = 0; s_pos = 0;
    }
    __syncthreads();

    int match = (g_kidx[tid] == s_q) ? 1 : 0;
    if (match) atomicAdd(&s_cnt, 1);
    __syncthreads();
    int count = s_cnt;

    if (count > 0) {
        g_mul[tid] = match ? ((float)OUTC / (float)count) : 0.f;
        if (match) { int pp = atomicAdd(&s_pos, 1); g_sel[pp] = tid; }
        if (tid == 0) g_active = count;
    } else {
        g_mul[tid] = 1.f;
        g_sel[tid] = tid;
        if (tid == 0) g_active = OUTC;
    }
}

__global__ void __launch_bounds__(256) fill_bias(float4* __restrict__ out,
                                                 const float* __restrict__ bias) {
    if (g_active == OUTC) return;   // conv writes every channel in this case
    int i = blockIdx.x * 256 + threadIdx.x;
#pragma unroll
    for (int t = 0; t < 16; t++) {
        int o = (i / 784) & 511;
        float b = __ldg(&bias[o]);
        out[i] = make_float4(b, b, b, b);
        i += 1568 * 256;
    }
}

// Build A fragment stream (round-6 layout, MT=128).
__global__ void __launch_bounds__(256) w2frag(const float* __restrict__ W) {
    const int mt  = blockIdx.x;      // 0..3
    const int it  = blockIdx.y;      // 0..71
    const int tid = threadIdx.x;
    const int active = g_active;
    uint32_t v[8];
#pragma unroll
    for (int j = 0; j < 8; j++) {
        int s     = tid * 8 + j;
        int kstep = s >> 10;
        int mtile = (s >> 7) & 7;
        int lane  = (s >> 2) & 31;
        int reg   = s & 3;
        int m  = mtile * 16 + (lane >> 2) + (reg & 1) * 8;
        int kl = kstep * 16 + (lane & 3) * 2 + ((reg >> 1) & 1) * 8;
        int k  = it * 32 + kl;
        int gi = mt * MT + m;
        int g  = (gi < active) ? g_sel[gi] : 0;
        float2 w2 = __ldg((const float2*)&W[(size_t)g * D_TOT + k]);
        v[j] = packh2(w2.x, w2.y);
    }
    uint32_t* dst = g_Wa + ((size_t)(mt * NITER + it)) * A_STAGE_U32 + tid * 8;
    *(uint4*)dst       = make_uint4(v[0], v[1], v[2], v[3]);
    *(uint4*)(dst + 4) = make_uint4(v[4], v[5], v[6], v[7]);
}

// x NCHW f32 -> g_xt tiled half (pair-interleaved per 16-group) + fused tap-max.
__global__ void __launch_bounds__(256) x2tile(const float* __restrict__ x) {
    __shared__ float sx[32][129];
    const int tid = threadIdx.x;
    const int kc  = blockIdx.y;         // channel chunk 0..7
    const int pg0 = blockIdx.x * 128;
#pragma unroll
    for (int e = 0; e < 16; e++) {
        int idx = tid + e * 256;
        int c_l = idx >> 7;
        int p_l = idx & 127;
        int pg  = pg0 + p_l;
        int n   = pg / HWX;
        int pi  = pg - n * HWX;
        sx[c_l][p_l] = __ldg(&x[((size_t)n * INC + kc * 32 + c_l) * HWX + pi]);
    }
    __syncthreads();
    // ---- tiled write (pair-interleaved) ----
#pragma unroll
    for (int e = 0; e < 2; e++) {
        int w  = tid + e * 256;         // 0..511 = 128 pix x 4 uint4
        int p_l = w >> 2;
        int q   = w & 3;                // uint4 index within 32ch
        int g16 = q >> 1;               // 16-ch group
        int s0  = (q & 1) * 4;          // starting u32 slot within group
        uint32_t u[4];
#pragma unroll
        for (int j = 0; j < 4; j++) {
            int s  = s0 + j;
            int c0 = g16 * 16 + ((s & 1) ? (s + 7) : s);
            u[j] = packh2(sx[c0][p_l], sx[c0 + 1][p_l]);
        }
        *(uint4*)&g_xt[((size_t)kc * NPIX + pg0 + p_l) * 32 + q * 8]
            = make_uint4(u[0], u[1], u[2], u[3]);
    }
    // ---- fused per-tap maxima over this block's 128 pixels ----
    {
        const int c_l = tid >> 3;       // 0..31
        const int sub = tid & 7;        // 8 threads per channel
        float m[9];
#pragma unroll
        for (int i = 0; i < 9; i++) m[i] = -1e30f;
#pragma unroll
        for (int e = 0; e < 16; e++) {
            int p_l = sub * 16 + e;
            int pg  = pg0 + p_l;
            int n   = pg / HWX;
            int pi  = pg - n * HWX;
            int r   = pi / 56;
            int s   = pi - r * 56;
            float v = sx[c_l][p_l];
            bool r0 = (r <= 54), r2 = (r >= 1), c0 = (s <= 54), c2 = (s >= 1);
            m[4] = fmaxf(m[4], v);
            if (r0) { m[1] = fmaxf(m[1], v); if (c0) m[0] = fmaxf(m[0], v); if (c2) m[2] = fmaxf(m[2], v); }
            if (c0) m[3] = fmaxf(m[3], v);
            if (c2) m[5] = fmaxf(m[5], v);
            if (r2) { m[7] = fmaxf(m[7], v); if (c0) m[6] = fmaxf(m[6], v); if (c2) m[8] = fmaxf(m[8], v); }
        }
#pragma unroll
        for (int q = 0; q < 9; q++) {
            float mv = m[q];
            mv = fmaxf(mv, __shfl_xor_sync(0xffffffffu, mv, 1));
            mv = fmaxf(mv, __shfl_xor_sync(0xffffffffu, mv, 2));
            mv = fmaxf(mv, __shfl_xor_sync(0xffffffffu, mv, 4));
            if (sub == 0)
                atomicMax(&g_maxenc[q * INC + kc * 32 + c_l], encf(mv));
        }
    }
}

// ============================ tensor-core conv ===============================
// A: direct LDG.128 from fragment-ordered g_Wa (L2-resident) into registers.
// Warp tile 32x64 (wm 0..3, wn 0..1): A redundancy 2x (was 4x).
// B: 4-stage B-only cp.async ring; LDS.64 fragments (pair-interleaved layout).
// k order: it -> tap = it>>3, cchunk = it&7, k0 = it*32 (bit-identical math).
__global__ void __launch_bounds__(256, 2) conv_mma(const float* __restrict__ bias,
                                                   float* __restrict__ out) {
    const int active = g_active;
    const int mt = blockIdx.x;
    if (mt * MT >= active) return;
    const int nt  = blockIdx.y;
    const int tid = threadIdx.x;
    const int wid  = tid >> 5;
    const int lane = tid & 31;
    const int wm = wid & 3;             // 0..3 (32 rows each)
    const int wn = wid >> 2;            // 0..1 (64 cols each)

    extern __shared__ __align__(16) uint32_t smem[];
    const uint32_t sbase = smem_u32(smem);

    // A fragment source: per warp-lane uint4 index within an iter's 2048-u32 block
    const uint4* aSrc = (const uint4*)(g_Wa + (size_t)mt * NITER * A_STAGE_U32);
    // idx(ks, mi) = ks*256 + (wm*2+mi)*32 + lane  (uint4 units)
    const int aIdx0 = (wm * 2) * 32 + lane;

    // B staging: thread -> pixel np = tid>>1, slot-half hs = tid&1 (32B each).
    const int np = tid >> 1;
    const int hs = tid & 1;
    const int p  = nt * NT + np;
    const int pn = p / HWX;
    const int prem = p - pn * HWX;
    const int py = prem / 56;
    const int px = prem - py * 56;
    const uint32_t bDst = (uint32_t)np * 96u + (uint32_t)hs * 32u;
    const __half* xtp = g_xt + ((size_t)pn * HWX + prem) * 32 + hs * 16;

    float acc[2][8][4];
#pragma unroll
    for (int i = 0; i < 2; i++)
#pragma unroll
        for (int j = 0; j < 8; j++)
#pragma unroll
            for (int r = 0; r < 4; r++) acc[i][j][r] = 0.f;

#define ISSUE_STAGE(IT) do {                                                   \
        const int _it = (IT);                                                  \
        const uint32_t _sb = sbase + (uint32_t)(_it % NSTAGE) * STAGE_BYTES;   \
        const int _tap = _it >> 3;                                             \
        const int _kc  = _it & 7;                                              \
        const int _kh  = (_tap * 11) >> 5;                                     \
        const int _kw  = _tap - 3 * _kh;                                       \
        const int _r   = py + _kh - 1;                                         \
        const int _s   = px + _kw - 1;                                         \
        const bool _ok = ((unsigned)_r < 56u) && ((unsigned)_s < 56u);         \
        const long _off = (long)_kc * NPIX + ((_kh - 1) * 56 + (_kw - 1));     \
        const __half* _src = _ok ? (xtp + _off * 32) : (const __half*)g_xt;    \
        const uint32_t _sz = _ok ? 16u : 0u;                                   \
        cp16z(_sb + bDst,      _src,     _sz);                                 \
        cp16z(_sb + bDst + 16, _src + 8, _sz);                                 \
        CP_COMMIT();                                                           \
    } while (0)

    ISSUE_STAGE(0);
    ISSUE_STAGE(1);
    ISSUE_STAGE(2);

#pragma unroll 1
    for (int it = 0; it < NITER; it++) {
        // ---- A fragments for both ksteps: direct LDG.128 from L2 ----
        const uint4* aIt = aSrc + (size_t)it * (A_STAGE_U32 / 4);
        uint4 a0[2], a1[2];
#pragma unroll
        for (int mi = 0; mi < 2; mi++) a0[mi] = __ldg(aIt + aIdx0 + mi * 32);
#pragma unroll
        for (int mi = 0; mi < 2; mi++) a1[mi] = __ldg(aIt + 256 + aIdx0 + mi * 32);

        if (it + 3 <= NITER) CP_WAIT(2);
        else if (it + 2 == NITER) CP_WAIT(1);
        else CP_WAIT(0);
        __syncthreads();

        if (it + 3 < NITER) ISSUE_STAGE(it + 3);

        const uint32_t st = (uint32_t)(it % NSTAGE) * STAGE_U32;
#pragma unroll
        for (int ks = 0; ks < 2; ks++) {
            uint32_t bf[8][2];
#pragma unroll
            for (int nj = 0; nj < 8; nj++) {
                const uint32_t bi = st
                    + (uint32_t)(wn * 64 + nj * 8 + (lane >> 2)) * 24u
                    + (uint32_t)(ks * 8 + (lane & 3) * 2);
                uint2 v = *(const uint2*)&smem[bi];
                bf[nj][0] = v.x; bf[nj][1] = v.y;
            }
            const uint4* aa = ks ? a1 : a0;
#pragma unroll
            for (int mi = 0; mi < 2; mi++) {
                uint32_t af[4] = {aa[mi].x, aa[mi].y, aa[mi].z, aa[mi].w};
#pragma unroll
                for (int nj = 0; nj < 8; nj++)
                    mma16(acc[mi][nj], af, bf[nj]);
            }
        }
    }

    // ---------------- epilogue ----------------
#pragma unroll
    for (int mi = 0; mi < 2; mi++) {
        const int row0 = wm * 32 + mi * 16 + (lane >> 2);
#pragma unroll
        for (int rp = 0; rp < 2; rp++) {
            const int m  = row0 + rp * 8;
            const int gi = mt * MT + m;
            if (gi >= active) continue;
            const int g  = g_sel[gi];
            const float mu = g_mul[g];
            const float bb = __ldg(&bias[g]);
#pragma unroll
            for (int nj = 0; nj < 8; nj++) {
                const int col = wn * 64 + nj * 8 + 2 * (lane & 3);
                const int pp  = nt * NT + col;
                const int n   = pp / HWX;
                const int rem = pp - n * HWX;
                float2 v;
                v.x = fmaf(mu, acc[mi][nj][rp * 2 + 0], bb);
                v.y = fmaf(mu, acc[mi][nj][rp * 2 + 1], bb);
                *(float2*)&out[((size_t)n * OUTC + g) * HWX + rem] = v;
            }
        }
    }
}

// ============================================================================
extern "C" void kernel_launch(void* const* d_in, const int* in_sizes, int n_in,
                              void* d_out, int out_size) {
    const float* x = nullptr;
    const float* W = nullptr;
    const float* bias = nullptr;
    const float* a = nullptr;
    for (int i = 0; i < n_in; i++) {
        if (in_sizes[i] == NIMG * INC * HWX)      x    = (const float*)d_in[i];
        else if (in_sizes[i] == OUTC * D_TOT)     W    = (const float*)d_in[i];
        else if (in_sizes[i] == OUTC)             bias = (const float*)d_in[i];
        else if (in_sizes[i] == D_TOT + 5)        a    = (const float*)d_in[i];
    }
    float* out = (float*)d_out;

    cudaFuncSetAttribute(conv_mma, cudaFuncAttributeMaxDynamicSharedMemorySize,
                         SMEM_BYTES);

    hash_kernels<<<OUTC, 256>>>(W, a);
    x2tile<<<dim3(NPIX / 128, 8), 256>>>(x);
    build_route<<<1, 512>>>(a);
    w2frag<<<dim3(4, NITER), 256>>>(W);
    fill_bias<<<1568, 256>>>((float4*)out, bias);
    conv_mma<<<dim3(4, NPIX / NT), 256, SMEM_BYTES>>>(bias, out);
}

// round 16
// speedup vs baseline: 1.0190x; 1.0190x over previous
#include <cuda_runtime.h>
#include <cuda_fp16.h>
#include <math.h>
#include <stdint.h>

#define D_TOT 2304
#define OUTC  512
#define INC   256
#define HWX   3136          // 56*56
#define NIMG  16
#define NPIX  (NIMG*HWX)    // 50176

#define NITER32 72          // 32-k chunks
#define NITER64 36          // pipeline iters (2 chunks per stage)
#define MT    128           // CTA M tile (channels)
#define NT    128           // CTA N tile (pixels)

// B-only 4-stage cp.async ring; stage = 2 chunks x 128 pixels x 64B = 16KB.
#define A_STAGE_U32 2048    // g_Wa per-32-chunk stride (unchanged layout)
#define CHUNK_U32   (128*16)            // 2048 u32 = 8KB per chunk
#define STAGE_U32   (2*CHUNK_U32)       // 4096
#define STAGE_BYTES (STAGE_U32*4)       // 16384
#define NSTAGE      4
#define SMEM_BYTES  (NSTAGE*STAGE_BYTES)   // 65536

// scratch (device globals: no allocation allowed)
__device__ int      g_kidx[OUTC];
__device__ unsigned g_maxenc[D_TOT];   // order-preserving encoded maxima
__device__ float    g_mul[OUTC];
__device__ int      g_sel[OUTC];
__device__ int      g_active;
// A fragment stream: [mt(4)][chunk(72)][2048 u32] = 2.36 MB (L2-resident)
__device__ __align__(16) uint32_t g_Wa[4 * NITER32 * A_STAGE_U32];
// x tiled half: [cchunk(8)][pixel(50176)][32 ch] = 25.7 MB (L2-resident)
// within-pixel u32 slot s = quad*4 + ks*2 + reg (both-kstep LDS.128 order)
__device__ __align__(16) __half g_xt[(size_t)8 * NPIX * 32];

// ============================ helpers ========================================
__device__ __forceinline__ uint32_t smem_u32(const void* p) {
    uint32_t a;
    asm("{ .reg .u64 t; cvta.to.shared.u64 t, %1; cvt.u32.u64 %0, t; }"
        : "=r"(a) : "l"(p));
    return a;
}
__device__ __forceinline__ void cp16z(uint32_t dst, const void* src, uint32_t sz) {
    asm volatile("cp.async.cg.shared.global [%0], [%1], 16, %2;"
                 :: "r"(dst), "l"(src), "r"(sz) : "memory");
}
#define CP_COMMIT() asm volatile("cp.async.commit_group;" ::: "memory")
#define CP_WAIT(n)  asm volatile("cp.async.wait_group %0;" :: "n"(n) : "memory")

__device__ __forceinline__ uint32_t packh2(float lo, float hi) {
    __half2 h = __floats2half2_rn(lo, hi);
    return *reinterpret_cast<uint32_t*>(&h);
}
__device__ __forceinline__ void mma16(float* c, const uint32_t* a,
                                      uint32_t b0, uint32_t b1) {
    asm volatile(
        "mma.sync.aligned.m16n8k16.row.col.f32.f16.f16.f32 "
        "{%0,%1,%2,%3}, {%4,%5,%6,%7}, {%8,%9}, {%0,%1,%2,%3};\n"
        : "+f"(c[0]), "+f"(c[1]), "+f"(c[2]), "+f"(c[3])
        : "r"(a[0]), "r"(a[1]), "r"(a[2]), "r"(a[3]), "r"(b0), "r"(b1));
}
// order-preserving float<->uint encoding (monotone under unsigned compare)
__device__ __forceinline__ unsigned encf(float f) {
    int i = __float_as_int(f);
    return (i >= 0) ? ((unsigned)i ^ 0x80000000u) : ~(unsigned)i;
}
__device__ __forceinline__ float decf(unsigned u) {
    return (u & 0x80000000u) ? __int_as_float((int)(u ^ 0x80000000u))
                             : __int_as_float((int)~u);
}

// ============================ small kernels ==================================
__global__ void __launch_bounds__(256) hash_kernels(const float* __restrict__ W,
                                                    const float* __restrict__ a) {
    const int o   = blockIdx.x;
    const int tid = threadIdx.x;
    if (o == 0) {
        for (int i = tid; i < D_TOT; i += 256) g_maxenc[i] = 0u;
    }
    const float* w = W + (size_t)o * D_TOT;
    float dot = 0.f, n2 = 0.f;
    for (int i = tid; i < D_TOT; i += 256) {
        float v = w[i];
        dot += a[i] * v;
        n2  += v * v;
    }
    __shared__ float s1[256], s2[256];
    s1[tid] = dot; s2[tid] = n2;
    __syncthreads();
    for (int st = 128; st > 0; st >>= 1) {
        if (tid < st) { s1[tid] += s1[tid+st]; s2[tid] += s2[tid+st]; }
        __syncthreads();
    }
    if (tid == 0) {
        float acc = s1[0];
        float pw  = s2[0];
        acc += a[D_TOT+0] * pw; pw *= pw;
        acc += a[D_TOT+1] * pw; pw *= pw;
        acc += a[D_TOT+2] * pw; pw *= pw;
        acc += a[D_TOT+3] * pw; pw *= pw;
        acc += a[D_TOT+4] * pw;
        float h = floorf(acc);
        float r = fmodf(h, 16.f);
        if (r < 0.f) r += 16.f;
        g_kidx[o] = (int)r;
    }
}

__global__ void __launch_bounds__(512) build_route(const float* __restrict__ a) {
    const int tid = threadIdx.x;
    __shared__ float red[512];

    float v0[5];
#pragma unroll
    for (int e = 0; e < 5; e++) {
        int i = tid + e * 512;
        float v = 0.f;
        if (i < D_TOT) {
            v = decf(g_maxenc[i]);
            if ((i >> 8) != 4) v = fmaxf(v, 0.f);
        }
        v0[e] = v;
    }

    float ss = 0.f;
#pragma unroll
    for (int e = 0; e < 5; e++) ss += v0[e] * v0[e];
    red[tid] = ss; __syncthreads();
    for (int st = 256; st > 0; st >>= 1) { if (tid < st) red[tid] += red[tid+st]; __syncthreads(); }
    __shared__ float s_norm;
    if (tid == 0) s_norm = sqrtf(red[0]);
    __syncthreads();

    float dot = 0.f;
#pragma unroll
    for (int e = 0; e < 5; e++) {
        int i = tid + e * 512;
        if (i < D_TOT) dot += a[i] * v0[e];
    }
    red[tid] = dot; __syncthreads();
    for (int st = 256; st > 0; st >>= 1) { if (tid < st) red[tid] += red[tid+st]; __syncthreads(); }

    __shared__ int s_q, s_cnt, s_pos;
    if (tid == 0) {
        float hs = 0.5f * (a[D_TOT] + a[D_TOT+1] + a[D_TOT+2] + a[D_TOT+3] + a[D_TOT+4]);
        float acc = red[0] / s_norm + hs;
        float h = floorf(acc);
        float r = fmodf(h, 16.f);
        if (r < 0.f) r += 16.f;
        s_q = (int)r;
        s_cnt = 0; s_pos = 0;
    }
    __syncthreads();

    int match = (g_kidx[tid] == s_q) ? 1 : 0;
    if (match) atomicAdd(&s_cnt, 1);
    __syncthreads();
    int count = s_cnt;

    if (count > 0) {
        g_mul[tid] = match ? ((float)OUTC / (float)count) : 0.f;
        if (match) { int pp = atomicAdd(&s_pos, 1); g_sel[pp] = tid; }
        if (tid == 0) g_active = count;
    } else {
        g_mul[tid] = 1.f;
        g_sel[tid] = tid;
        if (tid == 0) g_active = OUTC;
    }
}

__global__ void __launch_bounds__(256) fill_bias(float4* __restrict__ out,
                                                 const float* __restrict__ bias) {
    if (g_active == OUTC) return;   // conv writes every channel in this case
    int i = blockIdx.x * 256 + threadIdx.x;
#pragma unroll
    for (int t = 0; t < 16; t++) {
        int o = (i / 784) & 511;
        float b = __ldg(&bias[o]);
        out[i] = make_float4(b, b, b, b);
        i += 1568 * 256;
    }
}

// Build A fragment stream (round-6 layout, MT=128).
__global__ void __launch_bounds__(256) w2frag(const float* __restrict__ W) {
    const int mt  = blockIdx.x;      // 0..3
    const int it  = blockIdx.y;      // 0..71
    const int tid = threadIdx.x;
    const int active = g_active;
    uint32_t v[8];
#pragma unroll
    for (int j = 0; j < 8; j++) {
        int s     = tid * 8 + j;
        int kstep = s >> 10;
        int mtile = (s >> 7) & 7;
        int lane  = (s >> 2) & 31;
        int reg   = s & 3;
        int m  = mtile * 16 + (lane >> 2) + (reg & 1) * 8;
        int kl = kstep * 16 + (lane & 3) * 2 + ((reg >> 1) & 1) * 8;
        int k  = it * 32 + kl;
        int gi = mt * MT + m;
        int g  = (gi < active) ? g_sel[gi] : 0;
        float2 w2 = __ldg((const float2*)&W[(size_t)g * D_TOT + k]);
        v[j] = packh2(w2.x, w2.y);
    }
    uint32_t* dst = g_Wa + ((size_t)(mt * NITER32 + it)) * A_STAGE_U32 + tid * 8;
    *(uint4*)dst       = make_uint4(v[0], v[1], v[2], v[3]);
    *(uint4*)(dst + 4) = make_uint4(v[4], v[5], v[6], v[7]);
}

// x NCHW f32 -> g_xt tiled half + fused tap-max.
// Within-pixel u32 slot s = quad*4 + ks*2 + reg; content = channel pair
// c0 = ks*16 + (s_loc odd ? s_loc+7 : s_loc), s_loc = quad*2 + reg.
__global__ void __launch_bounds__(256) x2tile(const float* __restrict__ x) {
    __shared__ float sx[32][129];
    const int tid = threadIdx.x;
    const int kc  = blockIdx.y;         // channel chunk 0..7
    const int pg0 = blockIdx.x * 128;
#pragma unroll
    for (int e = 0; e < 16; e++) {
        int idx = tid + e * 256;
        int c_l = idx >> 7;
        int p_l = idx & 127;
        int pg  = pg0 + p_l;
        int n   = pg / HWX;
        int pi  = pg - n * HWX;
        sx[c_l][p_l] = __ldg(&x[((size_t)n * INC + kc * 32 + c_l) * HWX + pi]);
    }
    __syncthreads();
    // ---- tiled write (both-kstep LDS.128 slot order) ----
#pragma unroll
    for (int e = 0; e < 2; e++) {
        int w  = tid + e * 256;         // 0..511 = 128 pix x 4 uint4
        int p_l = w >> 2;
        int q   = w & 3;                // quad = uint4 index within pixel
        uint32_t u[4];
#pragma unroll
        for (int j = 0; j < 4; j++) {
            int grp   = j >> 1;         // kstep
            int s_loc = q * 2 + (j & 1);
            int c0 = grp * 16 + ((s_loc & 1) ? (s_loc + 7) : s_loc);
            u[j] = packh2(sx[c0][p_l], sx[c0 + 1][p_l]);
        }
        *(uint4*)&g_xt[((size_t)kc * NPIX + pg0 + p_l) * 32 + q * 8]
            = make_uint4(u[0], u[1], u[2], u[3]);
    }
    // ---- fused per-tap maxima over this block's 128 pixels ----
    {
        const int c_l = tid >> 3;       // 0..31
        const int sub = tid & 7;        // 8 threads per channel
        float m[9];
#pragma unroll
        for (int i = 0; i < 9; i++) m[i] = -1e30f;
#pragma unroll
        for (int e = 0; e < 16; e++) {
            int p_l = sub * 16 + e;
            int pg  = pg0 + p_l;
            int n   = pg / HWX;
            int pi  = pg - n * HWX;
            int r   = pi / 56;
            int s   = pi - r * 56;
            float v = sx[c_l][p_l];
            bool r0 = (r <= 54), r2 = (r >= 1), c0 = (s <= 54), c2 = (s >= 1);
            m[4] = fmaxf(m[4], v);
            if (r0) { m[1] = fmaxf(m[1], v); if (c0) m[0] = fmaxf(m[0], v); if (c2) m[2] = fmaxf(m[2], v); }
            if (c0) m[3] = fmaxf(m[3], v);
            if (c2) m[5] = fmaxf(m[5], v);
            if (r2) { m[7] = fmaxf(m[7], v); if (c0) m[6] = fmaxf(m[6], v); if (c2) m[8] = fmaxf(m[8], v); }
        }
#pragma unroll
        for (int q = 0; q < 9; q++) {
            float mv = m[q];
            mv = fmaxf(mv, __shfl_xor_sync(0xffffffffu, mv, 1));
            mv = fmaxf(mv, __shfl_xor_sync(0xffffffffu, mv, 2));
            mv = fmaxf(mv, __shfl_xor_sync(0xffffffffu, mv, 4));
            if (sub == 0)
                atomicMax(&g_maxenc[q * INC + kc * 32 + c_l], encf(mv));
        }
    }
}

// ============================ tensor-core conv ===============================
// A: chunk-wise LDG.128 from fragment-ordered g_Wa (L1/L2-resident).
// B: 4-stage B-only cp.async ring, 2 chunks per stage (BK=64);
//    one LDS.128 per n-tile covers both ksteps of a chunk.
// Warp tile 64x32 (round-14). k ascending -> bit-identical accumulation.
__global__ void __launch_bounds__(256, 2) conv_mma(const float* __restrict__ bias,
                                                   float* __restrict__ out) {
    const int active = g_active;
    const int mt = blockIdx.x;
    if (mt * MT >= active) return;
    const int nt  = blockIdx.y;
    const int tid = threadIdx.x;
    const int wid  = tid >> 5;
    const int lane = tid & 31;
    const int wm = wid & 1;             // 0..1 (64 rows)
    const int wn = wid >> 1;            // 0..3 (32 cols)

    extern __shared__ __align__(16) uint32_t smem[];
    const uint32_t sbase = smem_u32(smem);

    const uint4* aSrc = (const uint4*)(g_Wa + (size_t)mt * NITER32 * A_STAGE_U32);
    const int aIdx0 = (wm * 4) * 32 + lane;   // uint4 units; kstep1 at +256

    // B staging: thread -> pixel np = tid>>1, half hs = tid&1 (32B per chunk).
    const int np = tid >> 1;
    const int hs = tid & 1;
    const int p  = nt * NT + np;
    const int pn = p / HWX;
    const int prem = p - pn * HWX;
    const int py = prem / 56;
    const int px = prem - py * 56;
    const uint32_t bDst = (uint32_t)np * 64u + (uint32_t)hs * 32u;
    const __half* xtp = g_xt + ((size_t)pn * HWX + prem) * 32 + hs * 16;

    // B fragment base (u32): pixel stride 16, quad offset (lane&3)*4
    const uint32_t bRd = (uint32_t)(wn * 32 + (lane >> 2)) * 16u
                       + (uint32_t)(lane & 3) * 4u;

    float acc[4][4][4];
#pragma unroll
    for (int i = 0; i < 4; i++)
#pragma unroll
        for (int j = 0; j < 4; j++)
#pragma unroll
            for (int r = 0; r < 4; r++) acc[i][j][r] = 0.f;

#define ISSUE_STAGE(IT) do {                                                   \
        const int _it = (IT);                                                  \
        const uint32_t _sb = sbase + (uint32_t)(_it % NSTAGE) * STAGE_BYTES;   \
        const int _tap = _it >> 2;                                             \
        const int _kc0 = (_it & 3) * 2;                                        \
        const int _kh  = (_tap * 11) >> 5;                                     \
        const int _kw  = _tap - 3 * _kh;                                       \
        const int _r   = py + _kh - 1;                                         \
        const int _s   = px + _kw - 1;                                         \
        const bool _ok = ((unsigned)_r < 56u) && ((unsigned)_s < 56u);         \
        const long _tr = (_kh - 1) * 56 + (_kw - 1);                           \
        const __half* _s0 = _ok ? (xtp + ((long)_kc0 * NPIX + _tr) * 32)       \
                                : (const __half*)g_xt;                         \
        const __half* _s1 = _ok ? (xtp + ((long)(_kc0 + 1) * NPIX + _tr) * 32) \
                                : (const __half*)g_xt;                         \
        const uint32_t _sz = _ok ? 16u : 0u;                                   \
        cp16z(_sb + bDst,             _s0,     _sz);                           \
        cp16z(_sb + bDst + 16,        _s0 + 8, _sz);                           \
        cp16z(_sb + 8192u + bDst,      _s1,     _sz);                          \
        cp16z(_sb + 8192u + bDst + 16, _s1 + 8, _sz);                          \
        CP_COMMIT();                                                           \
    } while (0)

    ISSUE_STAGE(0);
    ISSUE_STAGE(1);
    ISSUE_STAGE(2);

#pragma unroll 1
    for (int it = 0; it < NITER64; it++) {
        if (it + 3 <= NITER64) CP_WAIT(2);
        else if (it + 2 == NITER64) CP_WAIT(1);
        else CP_WAIT(0);
        __syncthreads();

        if (it + 3 < NITER64) ISSUE_STAGE(it + 3);

        const uint32_t st = (uint32_t)(it % NSTAGE) * STAGE_U32;
#pragma unroll
        for (int cb = 0; cb < 2; cb++) {
            // ---- A fragments (both ksteps of this chunk): LDG.128 ----
            const uint4* aIt = aSrc + (size_t)(2 * it + cb) * 512;
            uint4 a0[4], a1[4];
#pragma unroll
            for (int j = 0; j < 4; j++) a0[j] = __ldg(aIt + aIdx0 + j * 32);
#pragma unroll
            for (int j = 0; j < 4; j++) a1[j] = __ldg(aIt + 256 + aIdx0 + j * 32);

            // ---- B fragments: one LDS.128 per n-tile covers both ksteps ----
            const uint32_t bb = st + (uint32_t)cb * CHUNK_U32;
            uint4 bq[4];
#pragma unroll
            for (int nj = 0; nj < 4; nj++)
                bq[nj] = *(const uint4*)&smem[bb + bRd + (uint32_t)nj * 128u];

#pragma unroll
            for (int mi = 0; mi < 4; mi++) {
                uint32_t af[4] = {a0[mi].x, a0[mi].y, a0[mi].z, a0[mi].w};
#pragma unroll
                for (int nj = 0; nj < 4; nj++)
                    mma16(acc[mi][nj], af, bq[nj].x, bq[nj].y);
            }
#pragma unroll
            for (int mi = 0; mi < 4; mi++) {
                uint32_t af[4] = {a1[mi].x, a1[mi].y, a1[mi].z, a1[mi].w};
#pragma unroll
                for (int nj = 0; nj < 4; nj++)
                    mma16(acc[mi][nj], af, bq[nj].z, bq[nj].w);
            }
        }
    }

    // ---------------- epilogue ----------------
#pragma unroll
    for (int mi = 0; mi < 4; mi++) {
        const int row0 = wm * 64 + mi * 16 + (lane >> 2);
#pragma unroll
        for (int rp = 0; rp < 2; rp++) {
            const int m  = row0 + rp * 8;
            const int gi = mt * MT + m;
            if (gi >= active) continue;
            const int g  = g_sel[gi];
            const float mu = g_mul[g];
            const float bb = __ldg(&bias[g]);
#pragma unroll
            for (int nj = 0; nj < 4; nj++) {
                const int col = wn * 32 + nj * 8 + 2 * (lane & 3);
                const int pp  = nt * NT + col;
                const int n   = pp / HWX;
                const int rem = pp - n * HWX;
                float2 v;
                v.x = fmaf(mu, acc[mi][nj][rp * 2 + 0], bb);
                v.y = fmaf(mu, acc[mi][nj][rp * 2 + 1], bb);
                *(float2*)&out[((size_t)n * OUTC + g) * HWX + rem] = v;
            }
        }
    }
}

// ============================================================================
extern "C" void kernel_launch(void* const* d_in, const int* in_sizes, int n_in,
                              void* d_out, int out_size) {
    const float* x = nullptr;
    const float* W = nullptr;
    const float* bias = nullptr;
    const float* a = nullptr;
    for (int i = 0; i < n_in; i++) {
        if (in_sizes[i] == NIMG * INC * HWX)      x    = (const float*)d_in[i];
        else if (in_sizes[i] == OUTC * D_TOT)     W    = (const float*)d_in[i];
        else if (in_sizes[i] == OUTC)             bias = (const float*)d_in[i];
        else if (in_sizes[i] == D_TOT + 5)        a    = (const float*)d_in[i];
    }
    float* out = (float*)d_out;

    cudaFuncSetAttribute(conv_mma, cudaFuncAttributeMaxDynamicSharedMemorySize,
                         SMEM_BYTES);

    hash_kernels<<<OUTC, 256>>>(W, a);
    x2tile<<<dim3(NPIX / 128, 8), 256>>>(x);
    build_route<<<1, 512>>>(a);
    w2frag<<<dim3(4, NITER32), 256>>>(W);
    fill_bias<<<1568, 256>>>((float4*)out, bias);
    conv_mma<<<dim3(4, NPIX / NT), 256, SMEM_BYTES>>>(bias, out);
}

// round 17
// speedup vs baseline: 1.2157x; 1.1931x over previous
#include <cuda_runtime.h>
#include <cuda_fp16.h>
#include <math.h>
#include <stdint.h>

#define D_TOT 2304
#define OUTC  512
#define INC   256
#define HWX   3136          // 56*56
#define NIMG  16
#define NPIX  (NIMG*HWX)    // 50176

#define BK    32
#define NITER (D_TOT/BK)    // 72
#define MT    128           // CTA M tile (channels)
#define NT    128           // CTA N tile (pixels)

// B-only 4-stage cp.async ring (A streams L2->registers via LDG.128).
#define A_STAGE_U32 2048    // g_Wa per-iter stride (unchanged layout)
#define B_PIX_U32   24      // 16 used + 8 pad (conflict-free LDS.64 banks)
#define STAGE_U32   (128*B_PIX_U32)     // 3072
#define STAGE_BYTES (STAGE_U32*4)       // 12288
#define NSTAGE      4
#define SMEM_BYTES  (NSTAGE*STAGE_BYTES)   // 49152

// scratch (device globals: no allocation allowed)
__device__ int      g_kidx[OUTC];
__device__ unsigned g_maxenc[D_TOT];   // order-preserving encoded maxima
__device__ float    g_mul[OUTC];
__device__ int      g_sel[OUTC];
__device__ int      g_active;
// A fragment stream: [mt(4)][iter(72)][2048 u32] = 2.36 MB (L2-resident)
__device__ __align__(16) uint32_t g_Wa[4 * NITER * A_STAGE_U32];
// x tiled half, pair-interleaved per 16-group: [cchunk(8)][pixel][32ch] = 25.7 MB
__device__ __align__(16) __half g_xt[(size_t)8 * NPIX * 32];

// ============================ helpers ========================================
__device__ __forceinline__ uint32_t smem_u32(const void* p) {
    uint32_t a;
    asm("{ .reg .u64 t; cvta.to.shared.u64 t, %1; cvt.u32.u64 %0, t; }"
        : "=r"(a) : "l"(p));
    return a;
}
__device__ __forceinline__ void cp16z(uint32_t dst, const void* src, uint32_t sz) {
    asm volatile("cp.async.cg.shared.global [%0], [%1], 16, %2;"
                 :: "r"(dst), "l"(src), "r"(sz) : "memory");
}
#define CP_COMMIT() asm volatile("cp.async.commit_group;" ::: "memory")
#define CP_WAIT(n)  asm volatile("cp.async.wait_group %0;" :: "n"(n) : "memory")
#define NBAR(id)    asm volatile("bar.sync %0, 64;" :: "r"(id) : "memory")

__device__ __forceinline__ uint32_t packh2(float lo, float hi) {
    __half2 h = __floats2half2_rn(lo, hi);
    return *reinterpret_cast<uint32_t*>(&h);
}
__device__ __forceinline__ void mma16(float* c, const uint32_t* a, const uint32_t* b) {
    asm volatile(
        "mma.sync.aligned.m16n8k16.row.col.f32.f16.f16.f32 "
        "{%0,%1,%2,%3}, {%4,%5,%6,%7}, {%8,%9}, {%0,%1,%2,%3};\n"
        : "+f"(c[0]), "+f"(c[1]), "+f"(c[2]), "+f"(c[3])
        : "r"(a[0]), "r"(a[1]), "r"(a[2]), "r"(a[3]), "r"(b[0]), "r"(b[1]));
}
// order-preserving float<->uint encoding (monotone under unsigned compare)
__device__ __forceinline__ unsigned encf(float f) {
    int i = __float_as_int(f);
    return (i >= 0) ? ((unsigned)i ^ 0x80000000u) : ~(unsigned)i;
}
__device__ __forceinline__ float decf(unsigned u) {
    return (u & 0x80000000u) ? __int_as_float((int)(u ^ 0x80000000u))
                             : __int_as_float((int)~u);
}

// ============================ small kernels ==================================
__global__ void __launch_bounds__(256) hash_kernels(const float* __restrict__ W,
                                                    const float* __restrict__ a) {
    const int o   = blockIdx.x;
    const int tid = threadIdx.x;
    // re-init encoded maxima each launch (graph-replay safe; runs before x2tile)
    if (o == 0) {
        for (int i = tid; i < D_TOT; i += 256) g_maxenc[i] = 0u;
    }
    const float* w = W + (size_t)o * D_TOT;
    float dot = 0.f, n2 = 0.f;
    for (int i = tid; i < D_TOT; i += 256) {
        float v = w[i];
        dot += a[i] * v;
        n2  += v * v;
    }
    __shared__ float s1[256], s2[256];
    s1[tid] = dot; s2[tid] = n2;
    __syncthreads();
    for (int st = 128; st > 0; st >>= 1) {
        if (tid < st) { s1[tid] += s1[tid+st]; s2[tid] += s2[tid+st]; }
        __syncthreads();
    }
    if (tid == 0) {
        float acc = s1[0];
        float pw  = s2[0];
        acc += a[D_TOT+0] * pw; pw *= pw;
        acc += a[D_TOT+1] * pw; pw *= pw;
        acc += a[D_TOT+2] * pw; pw *= pw;
        acc += a[D_TOT+3] * pw; pw *= pw;
        acc += a[D_TOT+4] * pw;
        float h = floorf(acc);
        float r = fmodf(h, 16.f);
        if (r < 0.f) r += 16.f;
        g_kidx[o] = (int)r;
    }
}

__global__ void __launch_bounds__(512) build_route(const float* __restrict__ a) {
    const int tid = threadIdx.x;
    __shared__ float red[512];

    // decode maxima (+ pad-zero fmax for off-center taps)
    float v0[5];
#pragma unroll
    for (int e = 0; e < 5; e++) {
        int i = tid + e * 512;          // covers 2560 >= 2304
        float v = 0.f;
        if (i < D_TOT) {
            v = decf(g_maxenc[i]);
            if ((i >> 8) != 4) v = fmaxf(v, 0.f);
        }
        v0[e] = v;
    }

    float ss = 0.f;
#pragma unroll
    for (int e = 0; e < 5; e++) ss += v0[e] * v0[e];
    red[tid] = ss; __syncthreads();
    for (int st = 256; st > 0; st >>= 1) { if (tid < st) red[tid] += red[tid+st]; __syncthreads(); }
    __shared__ float s_norm;
    if (tid == 0) s_norm = sqrtf(red[0]);
    __syncthreads();

    float dot = 0.f;
#pragma unroll
    for (int e = 0; e < 5; e++) {
        int i = tid + e * 512;
        if (i < D_TOT) dot += a[i] * v0[e];
    }
    red[tid] = dot; __syncthreads();
    for (int st = 256; st > 0; st >>= 1) { if (tid < st) red[tid] += red[tid+st]; __syncthreads(); }

    __shared__ int s_q, s_cnt, s_pos;
    if (tid == 0) {
        float hs = 0.5f * (a[D_TOT] + a[D_TOT+1] + a[D_TOT+2] + a[D_TOT+3] + a[D_TOT+4]);
        float acc = red[0] / s_norm + hs;
        float h = floorf(acc);
        float r = fmodf(h, 16.f);
        if (r < 0.f) r += 16.f;
        s_q = (int)r;
        s_cnt = 0; s_pos = 0;
    }
    __syncthreads();

    int match = (g_kidx[tid] == s_q) ? 1 : 0;
    if (match) atomicAdd(&s_cnt, 1);
    __syncthreads();
    int count = s_cnt;

    if (count > 0) {
        g_mul[tid] = match ? ((float)OUTC / (float)count) : 0.f;
        if (match) { int pp = atomicAdd(&s_pos, 1); g_sel[pp] = tid; }
        if (tid == 0) g_active = count;
    } else {
        g_mul[tid] = 1.f;
        g_sel[tid] = tid;
        if (tid == 0) g_active = OUTC;
    }
}

__global__ void __launch_bounds__(256) fill_bias(float4* __restrict__ out,
                                                 const float* __restrict__ bias) {
    if (g_active == OUTC) return;   // conv writes every channel in this case
    int i = blockIdx.x * 256 + threadIdx.x;
#pragma unroll
    for (int t = 0; t < 16; t++) {
        int o = (i / 784) & 511;
        float b = __ldg(&bias[o]);
        out[i] = make_float4(b, b, b, b);
        i += 1568 * 256;
    }
}

// Build A fragment stream (round-6 layout, MT=128).
__global__ void __launch_bounds__(256) w2frag(const float* __restrict__ W) {
    const int mt  = blockIdx.x;      // 0..3
    const int it  = blockIdx.y;      // 0..71
    const int tid = threadIdx.x;
    const int active = g_active;
    uint32_t v[8];
#pragma unroll
    for (int j = 0; j < 8; j++) {
        int s     = tid * 8 + j;
        int kstep = s >> 10;
        int mtile = (s >> 7) & 7;
        int lane  = (s >> 2) & 31;
        int reg   = s & 3;
        int m  = mtile * 16 + (lane >> 2) + (reg & 1) * 8;
        int kl = kstep * 16 + (lane & 3) * 2 + ((reg >> 1) & 1) * 8;
        int k  = it * 32 + kl;
        int gi = mt * MT + m;
        int g  = (gi < active) ? g_sel[gi] : 0;
        float2 w2 = __ldg((const float2*)&W[(size_t)g * D_TOT + k]);
        v[j] = packh2(w2.x, w2.y);
    }
    uint32_t* dst = g_Wa + ((size_t)(mt * NITER + it)) * A_STAGE_U32 + tid * 8;
    *(uint4*)dst       = make_uint4(v[0], v[1], v[2], v[3]);
    *(uint4*)(dst + 4) = make_uint4(v[4], v[5], v[6], v[7]);
}

// x NCHW f32 -> g_xt tiled half (pair-interleaved per 16-group) + fused tap-max.
__global__ void __launch_bounds__(256) x2tile(const float* __restrict__ x) {
    __shared__ float sx[32][129];
    const int tid = threadIdx.x;
    const int kc  = blockIdx.y;         // channel chunk 0..7
    const int pg0 = blockIdx.x * 128;
#pragma unroll
    for (int e = 0; e < 16; e++) {
        int idx = tid + e * 256;
        int c_l = idx >> 7;
        int p_l = idx & 127;
        int pg  = pg0 + p_l;
        int n   = pg / HWX;
        int pi  = pg - n * HWX;
        sx[c_l][p_l] = __ldg(&x[((size_t)n * INC + kc * 32 + c_l) * HWX + pi]);
    }
    __syncthreads();
    // ---- tiled write (pair-interleaved) ----
#pragma unroll
    for (int e = 0; e < 2; e++) {
        int w  = tid + e * 256;         // 0..511 = 128 pix x 4 uint4
        int p_l = w >> 2;
        int q   = w & 3;                // uint4 index within 32ch
        int g16 = q >> 1;               // 16-ch group
        int s0  = (q & 1) * 4;          // starting u32 slot within group
        uint32_t u[4];
#pragma unroll
        for (int j = 0; j < 4; j++) {
            int s  = s0 + j;
            int c0 = g16 * 16 + ((s & 1) ? (s + 7) : s);
            u[j] = packh2(sx[c0][p_l], sx[c0 + 1][p_l]);
        }
        *(uint4*)&g_xt[((size_t)kc * NPIX + pg0 + p_l) * 32 + q * 8]
            = make_uint4(u[0], u[1], u[2], u[3]);
    }
    // ---- fused per-tap maxima over this block's 128 pixels ----
    {
        const int c_l = tid >> 3;       // 0..31
        const int sub = tid & 7;        // 8 threads per channel
        float m[9];
#pragma unroll
        for (int i = 0; i < 9; i++) m[i] = -1e30f;
#pragma unroll
        for (int e = 0; e < 16; e++) {
            int p_l = sub * 16 + e;
            int pg  = pg0 + p_l;
            int n   = pg / HWX;
            int pi  = pg - n * HWX;
            int r   = pi / 56;
            int s   = pi - r * 56;
            float v = sx[c_l][p_l];
            bool r0 = (r <= 54), r2 = (r >= 1), c0 = (s <= 54), c2 = (s >= 1);
            m[4] = fmaxf(m[4], v);
            if (r0) { m[1] = fmaxf(m[1], v); if (c0) m[0] = fmaxf(m[0], v); if (c2) m[2] = fmaxf(m[2], v); }
            if (c0) m[3] = fmaxf(m[3], v);
            if (c2) m[5] = fmaxf(m[5], v);
            if (r2) { m[7] = fmaxf(m[7], v); if (c0) m[6] = fmaxf(m[6], v); if (c2) m[8] = fmaxf(m[8], v); }
        }
#pragma unroll
        for (int q = 0; q < 9; q++) {
            float mv = m[q];
            mv = fmaxf(mv, __shfl_xor_sync(0xffffffffu, mv, 1));
            mv = fmaxf(mv, __shfl_xor_sync(0xffffffffu, mv, 2));
            mv = fmaxf(mv, __shfl_xor_sync(0xffffffffu, mv, 4));
            if (sub == 0)
                atomicMax(&g_maxenc[q * INC + kc * 32 + c_l], encf(mv));
        }
    }
}

// ============================ tensor-core conv ===============================
// Round-14 structure with PER-PAIR named barriers instead of __syncthreads:
// pixel group wn is staged by, and read by, exactly warps {2wn, 2wn+1}
// (threads [wn*64, wn*64+64)), so a 64-thread bar.sync(wn+1) suffices.
// A: direct LDG.128 from fragment-ordered g_Wa. B: 4-stage cp.async ring.
// k order: it -> tap = it>>3, cchunk = it&7, k0 = it*32 (bit-identical math).
__global__ void __launch_bounds__(256, 2) conv_mma(const float* __restrict__ bias,
                                                   float* __restrict__ out) {
    const int active = g_active;
    const int mt = blockIdx.x;
    if (mt * MT >= active) return;
    const int nt  = blockIdx.y;
    const int tid = threadIdx.x;
    const int wid  = tid >> 5;
    const int lane = tid & 31;
    const int wm = wid & 1;             // 0..1 (64 rows)
    const int wn = wid >> 1;            // 0..3 (32 cols)
    const int bar_id = wn + 1;          // named barrier per 64-thread pair

    extern __shared__ __align__(16) uint32_t smem[];
    const uint32_t sbase = smem_u32(smem);

    // A fragment source: per warp-lane uint4 index within an iter's 2048-u32 block
    const uint4* aSrc = (const uint4*)(g_Wa + (size_t)mt * NITER * A_STAGE_U32);
    // idx(ks, j) = ks*256 + (wm*4+j)*32 + lane
    const int aIdx0 = (wm * 4) * 32 + lane;

    // B staging: thread -> pixel np = tid>>1, slot-half hs = tid&1 (32B each).
    // np in [wn*32, wn*32+32) for this thread's pair (tid in [wn*64, wn*64+64)).
    const int np = tid >> 1;
    const int hs = tid & 1;
    const int p  = nt * NT + np;
    const int pn = p / HWX;
    const int prem = p - pn * HWX;
    const int py = prem / 56;
    const int px = prem - py * 56;
    const uint32_t bDst = (uint32_t)np * 96u + (uint32_t)hs * 32u;
    const __half* xtp = g_xt + ((size_t)pn * HWX + prem) * 32 + hs * 16;

    float acc[4][4][4];
#pragma unroll
    for (int i = 0; i < 4; i++)
#pragma unroll
        for (int j = 0; j < 4; j++)
#pragma unroll
            for (int r = 0; r < 4; r++) acc[i][j][r] = 0.f;

#define ISSUE_STAGE(IT) do {                                                   \
        const int _it = (IT);                                                  \
        const uint32_t _sb = sbase + (uint32_t)(_it % NSTAGE) * STAGE_BYTES;   \
        const int _tap = _it >> 3;                                             \
        const int _kc  = _it & 7;                                              \
        const int _kh  = (_tap * 11) >> 5;                                     \
        const int _kw  = _tap - 3 * _kh;                                       \
        const int _r   = py + _kh - 1;                                         \
        const int _s   = px + _kw - 1;                                         \
        const bool _ok = ((unsigned)_r < 56u) && ((unsigned)_s < 56u);         \
        const long _off = (long)_kc * NPIX + ((_kh - 1) * 56 + (_kw - 1));     \
        const __half* _src = _ok ? (xtp + _off * 32) : (const __half*)g_xt;    \
        const uint32_t _sz = _ok ? 16u : 0u;                                   \
        cp16z(_sb + bDst,      _src,     _sz);                                 \
        cp16z(_sb + bDst + 16, _src + 8, _sz);                                 \
        CP_COMMIT();                                                           \
    } while (0)

    ISSUE_STAGE(0);
    ISSUE_STAGE(1);
    ISSUE_STAGE(2);

#pragma unroll 1
    for (int it = 0; it < NITER; it++) {
        // ---- A fragments for both ksteps: direct LDG.128 from L2/L1 ----
        const uint4* aIt = aSrc + (size_t)it * (A_STAGE_U32 / 4);
        uint4 a0[4], a1[4];
#pragma unroll
        for (int j = 0; j < 4; j++) a0[j] = __ldg(aIt + aIdx0 + j * 32);
#pragma unroll
        for (int j = 0; j < 4; j++) a1[j] = __ldg(aIt + 256 + aIdx0 + j * 32);

        if (it + 3 <= NITER) CP_WAIT(2);
        else if (it + 2 == NITER) CP_WAIT(1);
        else CP_WAIT(0);
        NBAR(bar_id);   // sync only the 64-thread producer/consumer pair

        if (it + 3 < NITER) ISSUE_STAGE(it + 3);

        const uint32_t st = (uint32_t)(it % NSTAGE) * STAGE_U32;
#pragma unroll
        for (int ks = 0; ks < 2; ks++) {
            uint32_t bf[4][2];
#pragma unroll
            for (int nj = 0; nj < 4; nj++) {
                const uint32_t bi = st
                    + (uint32_t)(wn * 32 + nj * 8 + (lane >> 2)) * 24u
                    + (uint32_t)(ks * 8 + (lane & 3) * 2);
                uint2 v = *(const uint2*)&smem[bi];
                bf[nj][0] = v.x; bf[nj][1] = v.y;
            }
            const uint4* aa = ks ? a1 : a0;
#pragma unroll
            for (int mi = 0; mi < 4; mi++) {
                uint32_t af[4] = {aa[mi].x, aa[mi].y, aa[mi].z, aa[mi].w};
#pragma unroll
                for (int nj = 0; nj < 4; nj++)
                    mma16(acc[mi][nj], af, bf[nj]);
            }
        }
    }

    // ---------------- epilogue ----------------
#pragma unroll
    for (int mi = 0; mi < 4; mi++) {
        const int row0 = wm * 64 + mi * 16 + (lane >> 2);
#pragma unroll
        for (int rp = 0; rp < 2; rp++) {
            const int m  = row0 + rp * 8;
            const int gi = mt * MT + m;
            if (gi >= active) continue;
            const int g  = g_sel[gi];
            const float mu = g_mul[g];
            const float bb = __ldg(&bias[g]);
#pragma unroll
            for (int nj = 0; nj < 4; nj++) {
                const int col = wn * 32 + nj * 8 + 2 * (lane & 3);
                const int pp  = nt * NT + col;
                const int n   = pp / HWX;
                const int rem = pp - n * HWX;
                float2 v;
                v.x = fmaf(mu, acc[mi][nj][rp * 2 + 0], bb);
                v.y = fmaf(mu, acc[mi][nj][rp * 2 + 1], bb);
                *(float2*)&out[((size_t)n * OUTC + g) * HWX + rem] = v;
            }
        }
    }
}

// ============================================================================
extern "C" void kernel_launch(void* const* d_in, const int* in_sizes, int n_in,
                              void* d_out, int out_size) {
    const float* x = nullptr;
    const float* W = nullptr;
    const float* bias = nullptr;
    const float* a = nullptr;
    for (int i = 0; i < n_in; i++) {
        if (in_sizes[i] == NIMG * INC * HWX)      x    = (const float*)d_in[i];
        else if (in_sizes[i] == OUTC * D_TOT)     W    = (const float*)d_in[i];
        else if (in_sizes[i] == OUTC)             bias = (const float*)d_in[i];
        else if (in_sizes[i] == D_TOT + 5)        a    = (const float*)d_in[i];
    }
    float* out = (float*)d_out;

    cudaFuncSetAttribute(conv_mma, cudaFuncAttributeMaxDynamicSharedMemorySize,
                         SMEM_BYTES);

    hash_kernels<<<OUTC, 256>>>(W, a);
    x2tile<<<dim3(NPIX / 128, 8), 256>>>(x);
    build_route<<<1, 512>>>(a);
    w2frag<<<dim3(4, NITER), 256>>>(W);
    fill_bias<<<1568, 256>>>((float4*)out, bias);
    conv_mma<<<dim3(4, NPIX / NT), 256, SMEM_BYTES>>>(bias, out);
}